// round 14
// baseline (speedup 1.0000x reference)
#include <cuda_runtime.h>
#include <cmath>
#include <cstdint>

#define NN 8192
#define NB1 32
#define IBLK 32
#define ICH (NN/IBLK)      /* 256 */
#define JBLK 16
#define JPB (NN/JBLK)      /* 512  */

/* ---- k4 TMA config: KCH128/NST3 + distributed issue ---- */
#define BR 32              /* rows per block */
#define KCH 128            /* k-floats per chunk */
#define NST 3              /* pipeline stages */
#define KSPL 4
#define KPB (NN/KSPL)      /* 2048 */
#define NCH (KPB/KCH)      /* 16 chunks per block */
#define SM_W_OFF 128
#define SM_W_SZ  (NST*BR*KCH*4)               /* 49152 */
#define SM_CX_OFF (SM_W_OFF + SM_W_SZ)        /* 49280 */
#define SM_CS_OFF (SM_CX_OFF + NST*KCH*16)    /* 55424 */
#define SM_TOTAL  (SM_CS_OFF + NST*KCH*16)    /* 61568 */
#define NPROD (BR + 2)                        /* 34 producer threads */

typedef unsigned long long ull;

// ---------------- scratch (__device__ globals: no allocs allowed) ----------------
__device__ __align__(16) float4 g_XeT[NN];
__device__ __align__(16) float4 g_SeT[NN];
__device__ float g_bmax[NB1];
__device__ float g_nmax;
__device__ __align__(16) float4 g_pnum[2][IBLK][NN];
__device__ float g_pden[2][IBLK][NN];
__device__ __align__(16) float g_Xa[4*NN];
__device__ __align__(16) float g_Sa[4*NN];
__device__ __align__(16) float g_MxP[KSPL][4*NN];
__device__ __align__(16) float g_MsP[KSPL][4*NN];

// ---------------- small PTX helpers ----------------
__device__ __forceinline__ ull pk2(float lo, float hi){ ull r; asm("mov.b64 %0, {%1, %2};" : "=l"(r) : "f"(lo), "f"(hi)); return r; }
__device__ __forceinline__ float2 upk2(ull v){ float2 f; asm("mov.b64 {%0, %1}, %2;" : "=f"(f.x), "=f"(f.y) : "l"(v)); return f; }
__device__ __forceinline__ ull fma2(ull a, ull b, ull c){ ull d; asm("fma.rn.f32x2 %0, %1, %2, %3;" : "=l"(d) : "l"(a), "l"(b), "l"(c)); return d; }
__device__ __forceinline__ ull add2(ull a, ull b){ ull d; asm("add.rn.f32x2 %0, %1, %2;" : "=l"(d) : "l"(a), "l"(b)); return d; }
__device__ __forceinline__ ull ex2pair(ull g){
  ull e;
  asm("{\n\t.reg .f32 lo, hi;\n\t"
      "mov.b64 {lo, hi}, %1;\n\t"
      "ex2.approx.ftz.f32 lo, lo;\n\t"
      "ex2.approx.ftz.f32 hi, hi;\n\t"
      "mov.b64 %0, {lo, hi};\n\t}" : "=l"(e) : "l"(g));
  return e;
}
__device__ __forceinline__ uint32_t s2u(const void* p){
  uint32_t a; asm("{ .reg .u64 t; cvta.to.shared.u64 t, %1; cvt.u32.u64 %0, t; }" : "=r"(a) : "l"(p)); return a;
}
__device__ __forceinline__ void mbar_init(uint32_t m, uint32_t cnt){
  asm volatile("mbarrier.init.shared.b64 [%0], %1;" :: "r"(m), "r"(cnt) : "memory");
}
__device__ __forceinline__ void mbar_expect(uint32_t m, uint32_t bytes){
  asm volatile("mbarrier.arrive.expect_tx.shared.b64 _, [%0], %1;" :: "r"(m), "r"(bytes) : "memory");
}
__device__ __forceinline__ void mbar_wait(uint32_t m, uint32_t ph){
  uint32_t done;
  asm volatile("{\n\t.reg .pred p;\n\t"
    "mbarrier.try_wait.parity.acquire.cta.shared::cta.b64 p, [%1], %2;\n\t"
    "selp.b32 %0, 1, 0, p;\n\t}" : "=r"(done) : "r"(m), "r"(ph) : "memory");
  while(!done){
    asm volatile("{\n\t.reg .pred p;\n\t"
      "mbarrier.try_wait.parity.acquire.cta.shared::cta.b64 p, [%1], %2, 0x989680;\n\t"
      "selp.b32 %0, 1, 0, p;\n\t}" : "=r"(done) : "r"(m), "r"(ph) : "memory");
  }
}
__device__ __forceinline__ void bulk_g2s(uint32_t sdst, const void* gsrc, uint32_t bytes, uint32_t m){
  unsigned long long g;
  asm("cvta.to.global.u64 %0, %1;" : "=l"(g) : "l"(gsrc));
  asm volatile("cp.async.bulk.shared::cluster.global.mbarrier::complete_tx::bytes [%0], [%1], %2, [%3];"
    :: "r"(sdst), "l"(g), "r"(bytes), "r"(m) : "memory");
}

// ---------------- k1: Xe = W1x@S, Se = W1s@X, per-column norms, block max ----------------
__global__ void k1_embed(const float* __restrict__ X, const float* __restrict__ S,
                         const float* __restrict__ W1x, const float* __restrict__ W1s){
  int j = blockIdx.x*blockDim.x + threadIdx.x;
  float s0=S[j], s1=S[NN+j], s2=S[2*NN+j], s3=S[3*NN+j];
  float x0=X[j], x1=X[NN+j], x2=X[2*NN+j], x3=X[3*NN+j];
  float4 xe, se;
  xe.x = W1x[ 0]*s0 + W1x[ 1]*s1 + W1x[ 2]*s2 + W1x[ 3]*s3;
  xe.y = W1x[ 4]*s0 + W1x[ 5]*s1 + W1x[ 6]*s2 + W1x[ 7]*s3;
  xe.z = W1x[ 8]*s0 + W1x[ 9]*s1 + W1x[10]*s2 + W1x[11]*s3;
  xe.w = W1x[12]*s0 + W1x[13]*s1 + W1x[14]*s2 + W1x[15]*s3;
  se.x = W1s[ 0]*x0 + W1s[ 1]*x1 + W1s[ 2]*x2 + W1s[ 3]*x3;
  se.y = W1s[ 4]*x0 + W1s[ 5]*x1 + W1s[ 6]*x2 + W1s[ 7]*x3;
  se.z = W1s[ 8]*x0 + W1s[ 9]*x1 + W1s[10]*x2 + W1s[11]*x3;
  se.w = W1s[12]*x0 + W1s[13]*x1 + W1s[14]*x2 + W1s[15]*x3;
  g_XeT[j] = xe; g_SeT[j] = se;
  float nx = xe.x*xe.x + xe.y*xe.y + xe.z*xe.z + xe.w*xe.w;
  float ns = se.x*se.x + se.y*se.y + se.z*se.z + se.w*se.w;
  float m = sqrtf(fmaxf(nx, ns));
  __shared__ float red[256];
  red[threadIdx.x] = m; __syncthreads();
  for (int s = 128; s > 0; s >>= 1){
    if (threadIdx.x < s) red[threadIdx.x] = fmaxf(red[threadIdx.x], red[threadIdx.x+s]);
    __syncthreads();
  }
  if (threadIdx.x == 0) g_bmax[blockIdx.x] = red[0];
}

// ---------------- k1b: reduce block maxes -> single Nmax ----------------
__global__ void k1b_nmax(){
  float m = g_bmax[threadIdx.x];
  #pragma unroll
  for (int s = 16; s > 0; s >>= 1) m = fmaxf(m, __shfl_xor_sync(0xffffffffu, m, s));
  if (threadIdx.x == 0) g_nmax = m;
}

// ---------------- k2: rank-4 streaming softmax-attention partials (f32x2 over i-pairs) ----------------
__global__ void k2_attn(){
  const int jb = blockIdx.x, ib = blockIdx.y, br = blockIdx.z;
  const float4* __restrict__ E = br ? g_SeT : g_XeT;
  __shared__ float shX[ICH], shY[ICH], shZ[ICH], shW[ICH];

  const float Nmax = g_nmax;

  const int ibase = ib*ICH;
  for (int t = threadIdx.x; t < ICH; t += blockDim.x){
    float4 v = E[ibase + t];
    shX[t]=v.x; shY[t]=v.y; shZ[t]=v.z; shW[t]=v.w;
  }
  __syncthreads();

  const float L2E = 1.4426950408889634f;
  const int j0 = jb*JPB + threadIdx.x;
  const int j1 = j0 + 256;
  float4 q0 = E[j0], q1 = E[j1];
  float c0 = sqrtf(q0.x*q0.x+q0.y*q0.y+q0.z*q0.z+q0.w*q0.w) * Nmax * L2E;
  float c1 = sqrtf(q1.x*q1.x+q1.y*q1.y+q1.z*q1.z+q1.w*q1.w) * Nmax * L2E;
  ull qx0 = pk2(q0.x*L2E, q0.x*L2E), qy0 = pk2(q0.y*L2E, q0.y*L2E);
  ull qz0 = pk2(q0.z*L2E, q0.z*L2E), qw0 = pk2(q0.w*L2E, q0.w*L2E);
  ull qx1 = pk2(q1.x*L2E, q1.x*L2E), qy1 = pk2(q1.y*L2E, q1.y*L2E);
  ull qz1 = pk2(q1.z*L2E, q1.z*L2E), qw1 = pk2(q1.w*L2E, q1.w*L2E);
  ull cc0 = pk2(-c0, -c0), cc1 = pk2(-c1, -c1);

  ull d0 = 0ull, d1 = 0ull;
  ull n0x=0ull, n0y=0ull, n0z=0ull, n0w=0ull;
  ull n1x=0ull, n1y=0ull, n1z=0ull, n1w=0ull;

  const ull* sX = (const ull*)shX; const ull* sY = (const ull*)shY;
  const ull* sZ = (const ull*)shZ; const ull* sW = (const ull*)shW;

  #pragma unroll 8
  for (int ii = 0; ii < ICH/2; ii++){
    ull sx = sX[ii], sy = sY[ii], sz = sZ[ii], sw = sW[ii];
    ull g0 = fma2(qx0, sx, fma2(qy0, sy, fma2(qz0, sz, fma2(qw0, sw, cc0))));
    ull e0 = ex2pair(g0);
    d0  = add2(d0, e0);
    n0x = fma2(sx, e0, n0x); n0y = fma2(sy, e0, n0y);
    n0z = fma2(sz, e0, n0z); n0w = fma2(sw, e0, n0w);
    ull g1 = fma2(qx1, sx, fma2(qy1, sy, fma2(qz1, sz, fma2(qw1, sw, cc1))));
    ull e1 = ex2pair(g1);
    d1  = add2(d1, e1);
    n1x = fma2(sx, e1, n1x); n1y = fma2(sy, e1, n1y);
    n1z = fma2(sz, e1, n1z); n1w = fma2(sw, e1, n1w);
  }

  float2 t2; float4 p;
  t2 = upk2(n0x); p.x = t2.x + t2.y;
  t2 = upk2(n0y); p.y = t2.x + t2.y;
  t2 = upk2(n0z); p.z = t2.x + t2.y;
  t2 = upk2(n0w); p.w = t2.x + t2.y;
  g_pnum[br][ib][j0] = p;
  t2 = upk2(d0);  g_pden[br][ib][j0] = t2.x + t2.y;

  t2 = upk2(n1x); p.x = t2.x + t2.y;
  t2 = upk2(n1y); p.y = t2.x + t2.y;
  t2 = upk2(n1z); p.z = t2.x + t2.y;
  t2 = upk2(n1w); p.w = t2.x + t2.y;
  g_pnum[br][ib][j1] = p;
  t2 = upk2(d1);  g_pden[br][ib][j1] = t2.x + t2.y;
}

// ---------------- k3: combine partials (coalesced: warp = 32 consecutive j, warp-id = q) ----------------
__global__ void k3_combine(){
  __shared__ float4 s_n[8][32];
  __shared__ float  s_d[8][32];
  const int bid  = blockIdx.x;          // 0..511
  const int br   = bid >> 8;            // 0..1
  const int j    = (bid & 255)*32 + (threadIdx.x & 31);
  const int q    = threadIdx.x >> 5;    // warp id = eighth of ib range
  float4 n = make_float4(0.f,0.f,0.f,0.f); float d = 0.f;
  #pragma unroll
  for (int i = 0; i < IBLK/8; i++){
    int ib = q*(IBLK/8) + i;
    float4 p = g_pnum[br][ib][j];       // 32 lanes -> 512B contiguous
    n.x += p.x; n.y += p.y; n.z += p.z; n.w += p.w;
    d += g_pden[br][ib][j];             // 128B contiguous
  }
  s_n[q][threadIdx.x & 31] = n;
  s_d[q][threadIdx.x & 31] = d;
  __syncthreads();
  if (q == 0){
    const int l = threadIdx.x & 31;
    float4 a = s_n[0][l]; float dd = s_d[0][l];
    #pragma unroll
    for (int k = 1; k < 8; k++){
      float4 p = s_n[k][l];
      a.x += p.x; a.y += p.y; a.z += p.z; a.w += p.w;
      dd += s_d[k][l];
    }
    float inv = 1.0f / dd;
    float* out = br ? g_Sa : g_Xa;
    out[0*NN+j] = a.x*inv; out[1*NN+j] = a.y*inv;
    out[2*NN+j] = a.z*inv; out[3*NN+j] = a.w*inv;
  }
}

// ---------------- k4: M = W2 @ C; TMA-1D 3-stage pipeline, split-K x4, distributed issue ----------------
__global__ void __launch_bounds__(256, 3) k4_gemv(const float* __restrict__ W2){
  extern __shared__ __align__(16) char smem[];
  const int tid = threadIdx.x;
  const int warp = tid >> 5, lane = tid & 31;
  const int ks = blockIdx.y;
  const int kbeg = ks*KPB;
  const int rb0 = blockIdx.x*BR;          // block's first row
  const int rbase = rb0 + warp*4;         // this warp's 4 rows

  const uint32_t mb = s2u(smem);          // full[st] at mb + st*8

  if (tid == 0){
    #pragma unroll
    for (int st = 0; st < NST; st++) mbar_init(mb + st*8, NPROD);
  }
  __syncthreads();

  // distributed issue: threads 0..31 copy one W row each; 32,33 copy the C tiles.
  auto issue = [&](int c){
    const int st = c % NST;
    const uint32_t m = mb + st*8;
    const int kc = kbeg + c*KCH;
    if (tid < BR){
      mbar_expect(m, KCH*4);
      const uint32_t wdst = s2u(smem + SM_W_OFF) + st*(BR*KCH*4) + tid*(KCH*4);
      bulk_g2s(wdst, W2 + (size_t)(rb0 + tid)*NN + kc, KCH*4, m);
    } else if (tid == BR){
      mbar_expect(m, KCH*16);
      bulk_g2s(s2u(smem + SM_CX_OFF) + st*(KCH*16), &g_Xa[(size_t)kc*4], KCH*16, m);
    } else if (tid == BR + 1){
      mbar_expect(m, KCH*16);
      bulk_g2s(s2u(smem + SM_CS_OFF) + st*(KCH*16), &g_Sa[(size_t)kc*4], KCH*16, m);
    }
  };

  issue(0); issue(1); issue(2);

  ull acc[4][4];
  #pragma unroll
  for (int r = 0; r < 4; r++)
    #pragma unroll
    for (int j = 0; j < 4; j++) acc[r][j] = 0ull;

  for (int c = 0; c < NCH; c++){
    const int st = c % NST;
    mbar_wait(mb + st*8, (c/NST) & 1);
    const float* w4 = (const float*)(smem + SM_W_OFF) + st*(BR*KCH) + warp*4*KCH;
    const float4* cx = (const float4*)(smem + SM_CX_OFF) + st*KCH;
    const float4* cs = (const float4*)(smem + SM_CS_OFF) + st*KCH;
    #pragma unroll
    for (int kk = 0; kk < KCH; kk += 64){
      const int k0 = kk + lane;
      const int k1 = k0 + 32;
      float w0[4], w1[4];
      #pragma unroll
      for (int r = 0; r < 4; r++){
        w0[r] = w4[r*KCH + k0];
        w1[r] = w4[r*KCH + k1];
      }
      {
        ulonglong2 vx = *(const ulonglong2*)&cx[k0];
        ulonglong2 vs = *(const ulonglong2*)&cs[k0];
        #pragma unroll
        for (int r = 0; r < 4; r++){
          ull wl = pk2(w0[r], w0[r]);
          acc[r][0] = fma2(wl, vx.x, acc[r][0]);
          acc[r][1] = fma2(wl, vx.y, acc[r][1]);
          acc[r][2] = fma2(wl, vs.x, acc[r][2]);
          acc[r][3] = fma2(wl, vs.y, acc[r][3]);
        }
      }
      {
        ulonglong2 vx = *(const ulonglong2*)&cx[k1];
        ulonglong2 vs = *(const ulonglong2*)&cs[k1];
        #pragma unroll
        for (int r = 0; r < 4; r++){
          ull wl = pk2(w1[r], w1[r]);
          acc[r][0] = fma2(wl, vx.x, acc[r][0]);
          acc[r][1] = fma2(wl, vx.y, acc[r][1]);
          acc[r][2] = fma2(wl, vs.x, acc[r][2]);
          acc[r][3] = fma2(wl, vs.y, acc[r][3]);
        }
      }
    }
    __syncthreads();
    if (c + NST < NCH) issue(c + NST);
  }

  #pragma unroll
  for (int r = 0; r < 4; r++){
    #pragma unroll
    for (int j = 0; j < 4; j++){
      ull v = acc[r][j];
      v = add2(v, __shfl_xor_sync(0xffffffffu, v, 16));
      v = add2(v, __shfl_xor_sync(0xffffffffu, v, 8));
      v = add2(v, __shfl_xor_sync(0xffffffffu, v, 4));
      v = add2(v, __shfl_xor_sync(0xffffffffu, v, 2));
      v = add2(v, __shfl_xor_sync(0xffffffffu, v, 1));
      if (lane == 0){
        float2 f = upk2(v);
        int row = rbase + r;
        if (j < 2){ g_MxP[ks][row*4 + 2*j]     = f.x; g_MxP[ks][row*4 + 2*j + 1]     = f.y; }
        else      { g_MsP[ks][row*4 + 2*(j-2)] = f.x; g_MsP[ks][row*4 + 2*(j-2) + 1] = f.y; }
      }
    }
  }
}

// ---------------- k5: gates + sinusoid + dual conv; sums split-K partials inline ----------------
__global__ void k5_conv(const float* __restrict__ X, const float* __restrict__ S,
                        const float* __restrict__ wx, const float* __restrict__ bx,
                        const float* __restrict__ ws, const float* __restrict__ bs,
                        float* __restrict__ out){
  __shared__ float in_s[2][8][258];
  __shared__ float wmid[2][8][8][3];
  __shared__ float bias[2][8];
  __shared__ float sins[258];
  const int t = threadIdx.x;
  const int n0 = blockIdx.x*256;

  for (int idx = t; idx < 384; idx += 256){
    int b = idx/192, rem = idx%192;
    int co = rem/24, ci = (rem%24)/3, kh = rem%3;
    const float* w = b ? ws : wx;
    wmid[b][co][ci][kh] = w[((co*8 + ci)*3 + kh)*3 + 1];
  }
  if (t < 16) bias[t>>3][t&7] = (t < 8) ? bx[t] : bs[t-8];
  for (int col = t; col < 258; col += 256)
    sins[col] = (float)sin((double)(n0 + col - 1));
  __syncthreads();

  for (int idx = t; idx < 2*8*258; idx += 256){
    int b = idx/(8*258); int rem = idx%(8*258);
    int ci = rem/258, col = rem%258;
    int n = n0 + col - 1;
    float v = 0.f;
    if (n >= 0 && n < NN){
      if (ci < 4){
        float m = 0.f;
        if (b == 0){
          #pragma unroll
          for (int ksp = 0; ksp < KSPL; ksp++) m += g_MxP[ksp][ci*NN + n];
        } else {
          #pragma unroll
          for (int ksp = 0; ksp < KSPL; ksp++) m += g_MsP[ksp][ci*NN + n];
        }
        v = m * X[ci*NN + n];
      } else {
        v = b ? S[(ci-4)*NN + n] : X[(ci-4)*NN + n];
      }
      if (b == 1) v += sins[col];
    }
    in_s[b][ci][col] = v;
  }
  __syncthreads();

  const int n = n0 + t;
  #pragma unroll
  for (int b = 0; b < 2; b++){
    #pragma unroll
    for (int co = 0; co < 8; co++){
      float a = bias[b][co];
      #pragma unroll
      for (int ci = 0; ci < 8; ci++){
        a = fmaf(wmid[b][co][ci][0], in_s[b][ci][t  ], a);
        a = fmaf(wmid[b][co][ci][1], in_s[b][ci][t+1], a);
        a = fmaf(wmid[b][co][ci][2], in_s[b][ci][t+2], a);
      }
      out[(size_t)b*8*NN + (size_t)co*NN + n] = a;
    }
  }
}

// ---------------- launch ----------------
extern "C" void kernel_launch(void* const* d_in, const int* in_sizes, int n_in,
                              void* d_out, int out_size){
  (void)in_sizes; (void)n_in; (void)out_size;
  const float* X   = (const float*)d_in[0];
  const float* S   = (const float*)d_in[1];
  const float* W1x = (const float*)d_in[2];
  const float* W1s = (const float*)d_in[3];
  const float* W2  = (const float*)d_in[4];
  const float* cwx = (const float*)d_in[5];
  const float* cbx = (const float*)d_in[6];
  const float* cws = (const float*)d_in[7];
  const float* cbs = (const float*)d_in[8];
  float* out = (float*)d_out;

  static int smem_set = 0;
  if (!smem_set){
    cudaFuncSetAttribute(k4_gemv, cudaFuncAttributeMaxDynamicSharedMemorySize, SM_TOTAL);
    smem_set = 1;
  }

  k1_embed  <<<NB1, 256>>>(X, S, W1x, W1s);
  k1b_nmax  <<<1, 32>>>();
  k2_attn   <<<dim3(JBLK, IBLK, 2), 256>>>();
  k3_combine<<<512, 256>>>();
  k4_gemv   <<<dim3(NN/BR, KSPL), 256, SM_TOTAL>>>(W2);
  k5_conv   <<<NN/256, 256>>>(X, S, cwx, cbx, cws, cbs, out);
}

// round 15
// speedup vs baseline: 1.0687x; 1.0687x over previous
#include <cuda_runtime.h>
#include <cmath>
#include <cstdint>

#define NN 8192
#define NB1 32
#define IBLK 32
#define ICH (NN/IBLK)      /* 256 */
#define JBLK 16
#define JPB (NN/JBLK)      /* 512  */

/* ---- k4 TMA config (R11/R13 proven: KCH256/NST2, distributed issue) ---- */
#define BR 32              /* rows per block */
#define KCH 256            /* k-floats per chunk */
#define NST 2              /* pipeline stages */
#define KSPL 4
#define KPB (NN/KSPL)      /* 2048 */
#define NCH (KPB/KCH)      /* 8 chunks per block */
#define SM_W_OFF 128
#define SM_W_SZ  (NST*BR*KCH*4)               /* 65536 */
#define SM_CX_OFF (SM_W_OFF + SM_W_SZ)        /* 65664 */
#define SM_CS_OFF (SM_CX_OFF + NST*KCH*16)    /* 73856 */
#define SM_TOTAL  (SM_CS_OFF + NST*KCH*16)    /* 82048 */
#define NPROD (BR + 2)                        /* 34 producer threads */

typedef unsigned long long ull;

// ---------------- scratch (__device__ globals: no allocs allowed) ----------------
__device__ __align__(16) float4 g_XeT[NN];
__device__ __align__(16) float4 g_SeT[NN];
__device__ float g_bmax[NB1];
__device__ float g_nmax;
__device__ __align__(16) float4 g_pnum[2][IBLK][NN];
__device__ float g_pden[2][IBLK][NN];
__device__ __align__(16) float g_Xa[4*NN];
__device__ __align__(16) float g_Sa[4*NN];
__device__ __align__(16) float g_MxP[KSPL][4*NN];
__device__ __align__(16) float g_MsP[KSPL][4*NN];

// ---------------- small PTX helpers ----------------
__device__ __forceinline__ ull pk2(float lo, float hi){ ull r; asm("mov.b64 %0, {%1, %2};" : "=l"(r) : "f"(lo), "f"(hi)); return r; }
__device__ __forceinline__ float2 upk2(ull v){ float2 f; asm("mov.b64 {%0, %1}, %2;" : "=f"(f.x), "=f"(f.y) : "l"(v)); return f; }
__device__ __forceinline__ ull fma2(ull a, ull b, ull c){ ull d; asm("fma.rn.f32x2 %0, %1, %2, %3;" : "=l"(d) : "l"(a), "l"(b), "l"(c)); return d; }
__device__ __forceinline__ ull add2(ull a, ull b){ ull d; asm("add.rn.f32x2 %0, %1, %2;" : "=l"(d) : "l"(a), "l"(b)); return d; }
__device__ __forceinline__ ull ex2pair(ull g){
  ull e;
  asm("{\n\t.reg .f32 lo, hi;\n\t"
      "mov.b64 {lo, hi}, %1;\n\t"
      "ex2.approx.ftz.f32 lo, lo;\n\t"
      "ex2.approx.ftz.f32 hi, hi;\n\t"
      "mov.b64 %0, {lo, hi};\n\t}" : "=l"(e) : "l"(g));
  return e;
}
__device__ __forceinline__ uint32_t s2u(const void* p){
  uint32_t a; asm("{ .reg .u64 t; cvta.to.shared.u64 t, %1; cvt.u32.u64 %0, t; }" : "=r"(a) : "l"(p)); return a;
}
__device__ __forceinline__ void mbar_init(uint32_t m, uint32_t cnt){
  asm volatile("mbarrier.init.shared.b64 [%0], %1;" :: "r"(m), "r"(cnt) : "memory");
}
__device__ __forceinline__ void mbar_expect(uint32_t m, uint32_t bytes){
  asm volatile("mbarrier.arrive.expect_tx.shared.b64 _, [%0], %1;" :: "r"(m), "r"(bytes) : "memory");
}
__device__ __forceinline__ void mbar_wait(uint32_t m, uint32_t ph){
  uint32_t done;
  asm volatile("{\n\t.reg .pred p;\n\t"
    "mbarrier.try_wait.parity.acquire.cta.shared::cta.b64 p, [%1], %2;\n\t"
    "selp.b32 %0, 1, 0, p;\n\t}" : "=r"(done) : "r"(m), "r"(ph) : "memory");
  while(!done){
    asm volatile("{\n\t.reg .pred p;\n\t"
      "mbarrier.try_wait.parity.acquire.cta.shared::cta.b64 p, [%1], %2, 0x989680;\n\t"
      "selp.b32 %0, 1, 0, p;\n\t}" : "=r"(done) : "r"(m), "r"(ph) : "memory");
  }
}
__device__ __forceinline__ void bulk_g2s(uint32_t sdst, const void* gsrc, uint32_t bytes, uint32_t m){
  unsigned long long g;
  asm("cvta.to.global.u64 %0, %1;" : "=l"(g) : "l"(gsrc));
  asm volatile("cp.async.bulk.shared::cluster.global.mbarrier::complete_tx::bytes [%0], [%1], %2, [%3];"
    :: "r"(sdst), "l"(g), "r"(bytes), "r"(m) : "memory");
}

// ---------------- k1: Xe = W1x@S, Se = W1s@X, per-column norms, block max ----------------
__global__ void k1_embed(const float* __restrict__ X, const float* __restrict__ S,
                         const float* __restrict__ W1x, const float* __restrict__ W1s){
  int j = blockIdx.x*blockDim.x + threadIdx.x;
  float s0=S[j], s1=S[NN+j], s2=S[2*NN+j], s3=S[3*NN+j];
  float x0=X[j], x1=X[NN+j], x2=X[2*NN+j], x3=X[3*NN+j];
  float4 xe, se;
  xe.x = W1x[ 0]*s0 + W1x[ 1]*s1 + W1x[ 2]*s2 + W1x[ 3]*s3;
  xe.y = W1x[ 4]*s0 + W1x[ 5]*s1 + W1x[ 6]*s2 + W1x[ 7]*s3;
  xe.z = W1x[ 8]*s0 + W1x[ 9]*s1 + W1x[10]*s2 + W1x[11]*s3;
  xe.w = W1x[12]*s0 + W1x[13]*s1 + W1x[14]*s2 + W1x[15]*s3;
  se.x = W1s[ 0]*x0 + W1s[ 1]*x1 + W1s[ 2]*x2 + W1s[ 3]*x3;
  se.y = W1s[ 4]*x0 + W1s[ 5]*x1 + W1s[ 6]*x2 + W1s[ 7]*x3;
  se.z = W1s[ 8]*x0 + W1s[ 9]*x1 + W1s[10]*x2 + W1s[11]*x3;
  se.w = W1s[12]*x0 + W1s[13]*x1 + W1s[14]*x2 + W1s[15]*x3;
  g_XeT[j] = xe; g_SeT[j] = se;
  float nx = xe.x*xe.x + xe.y*xe.y + xe.z*xe.z + xe.w*xe.w;
  float ns = se.x*se.x + se.y*se.y + se.z*se.z + se.w*se.w;
  float m = sqrtf(fmaxf(nx, ns));
  __shared__ float red[256];
  red[threadIdx.x] = m; __syncthreads();
  for (int s = 128; s > 0; s >>= 1){
    if (threadIdx.x < s) red[threadIdx.x] = fmaxf(red[threadIdx.x], red[threadIdx.x+s]);
    __syncthreads();
  }
  if (threadIdx.x == 0) g_bmax[blockIdx.x] = red[0];
}

// ---------------- k1b: reduce block maxes -> single Nmax ----------------
__global__ void k1b_nmax(){
  float m = g_bmax[threadIdx.x];
  #pragma unroll
  for (int s = 16; s > 0; s >>= 1) m = fmaxf(m, __shfl_xor_sync(0xffffffffu, m, s));
  if (threadIdx.x == 0) g_nmax = m;
}

// ---------------- k2: rank-4 streaming softmax-attention partials (f32x2 over i-pairs) ----------------
__global__ void k2_attn(){
  const int jb = blockIdx.x, ib = blockIdx.y, br = blockIdx.z;
  const float4* __restrict__ E = br ? g_SeT : g_XeT;
  __shared__ float shX[ICH], shY[ICH], shZ[ICH], shW[ICH];

  const float Nmax = g_nmax;

  const int ibase = ib*ICH;
  for (int t = threadIdx.x; t < ICH; t += blockDim.x){
    float4 v = E[ibase + t];
    shX[t]=v.x; shY[t]=v.y; shZ[t]=v.z; shW[t]=v.w;
  }
  __syncthreads();

  const float L2E = 1.4426950408889634f;
  const int j0 = jb*JPB + threadIdx.x;
  const int j1 = j0 + 256;
  float4 q0 = E[j0], q1 = E[j1];
  float c0 = sqrtf(q0.x*q0.x+q0.y*q0.y+q0.z*q0.z+q0.w*q0.w) * Nmax * L2E;
  float c1 = sqrtf(q1.x*q1.x+q1.y*q1.y+q1.z*q1.z+q1.w*q1.w) * Nmax * L2E;
  ull qx0 = pk2(q0.x*L2E, q0.x*L2E), qy0 = pk2(q0.y*L2E, q0.y*L2E);
  ull qz0 = pk2(q0.z*L2E, q0.z*L2E), qw0 = pk2(q0.w*L2E, q0.w*L2E);
  ull qx1 = pk2(q1.x*L2E, q1.x*L2E), qy1 = pk2(q1.y*L2E, q1.y*L2E);
  ull qz1 = pk2(q1.z*L2E, q1.z*L2E), qw1 = pk2(q1.w*L2E, q1.w*L2E);
  ull cc0 = pk2(-c0, -c0), cc1 = pk2(-c1, -c1);

  ull d0 = 0ull, d1 = 0ull;
  ull n0x=0ull, n0y=0ull, n0z=0ull, n0w=0ull;
  ull n1x=0ull, n1y=0ull, n1z=0ull, n1w=0ull;

  const ull* sX = (const ull*)shX; const ull* sY = (const ull*)shY;
  const ull* sZ = (const ull*)shZ; const ull* sW = (const ull*)shW;

  #pragma unroll 8
  for (int ii = 0; ii < ICH/2; ii++){
    ull sx = sX[ii], sy = sY[ii], sz = sZ[ii], sw = sW[ii];
    ull g0 = fma2(qx0, sx, fma2(qy0, sy, fma2(qz0, sz, fma2(qw0, sw, cc0))));
    ull e0 = ex2pair(g0);
    d0  = add2(d0, e0);
    n0x = fma2(sx, e0, n0x); n0y = fma2(sy, e0, n0y);
    n0z = fma2(sz, e0, n0z); n0w = fma2(sw, e0, n0w);
    ull g1 = fma2(qx1, sx, fma2(qy1, sy, fma2(qz1, sz, fma2(qw1, sw, cc1))));
    ull e1 = ex2pair(g1);
    d1  = add2(d1, e1);
    n1x = fma2(sx, e1, n1x); n1y = fma2(sy, e1, n1y);
    n1z = fma2(sz, e1, n1z); n1w = fma2(sw, e1, n1w);
  }

  float2 t2; float4 p;
  t2 = upk2(n0x); p.x = t2.x + t2.y;
  t2 = upk2(n0y); p.y = t2.x + t2.y;
  t2 = upk2(n0z); p.z = t2.x + t2.y;
  t2 = upk2(n0w); p.w = t2.x + t2.y;
  g_pnum[br][ib][j0] = p;
  t2 = upk2(d0);  g_pden[br][ib][j0] = t2.x + t2.y;

  t2 = upk2(n1x); p.x = t2.x + t2.y;
  t2 = upk2(n1y); p.y = t2.x + t2.y;
  t2 = upk2(n1z); p.z = t2.x + t2.y;
  t2 = upk2(n1w); p.w = t2.x + t2.y;
  g_pnum[br][ib][j1] = p;
  t2 = upk2(d1);  g_pden[br][ib][j1] = t2.x + t2.y;
}

// ---------------- k3: combine partials (coalesced: warp = 32 consecutive j, warp-id = q) ----------------
__global__ void k3_combine(){
  __shared__ float4 s_n[8][32];
  __shared__ float  s_d[8][32];
  const int bid  = blockIdx.x;          // 0..511
  const int br   = bid >> 8;            // 0..1
  const int j    = (bid & 255)*32 + (threadIdx.x & 31);
  const int q    = threadIdx.x >> 5;    // warp id = eighth of ib range
  float4 n = make_float4(0.f,0.f,0.f,0.f); float d = 0.f;
  #pragma unroll
  for (int i = 0; i < IBLK/8; i++){
    int ib = q*(IBLK/8) + i;
    float4 p = g_pnum[br][ib][j];       // 32 lanes -> 512B contiguous
    n.x += p.x; n.y += p.y; n.z += p.z; n.w += p.w;
    d += g_pden[br][ib][j];             // 128B contiguous
  }
  s_n[q][threadIdx.x & 31] = n;
  s_d[q][threadIdx.x & 31] = d;
  __syncthreads();
  if (q == 0){
    const int l = threadIdx.x & 31;
    float4 a = s_n[0][l]; float dd = s_d[0][l];
    #pragma unroll
    for (int k = 1; k < 8; k++){
      float4 p = s_n[k][l];
      a.x += p.x; a.y += p.y; a.z += p.z; a.w += p.w;
      dd += s_d[k][l];
    }
    float inv = 1.0f / dd;
    float* out = br ? g_Sa : g_Xa;
    out[0*NN+j] = a.x*inv; out[1*NN+j] = a.y*inv;
    out[2*NN+j] = a.z*inv; out[3*NN+j] = a.w*inv;
  }
}

// ---------------- k4: M = W2 @ C; TMA-1D pipeline, split-K x4, distributed issue ----------------
__global__ void __launch_bounds__(256, 2) k4_gemv(const float* __restrict__ W2){
  extern __shared__ __align__(16) char smem[];
  const int tid = threadIdx.x;
  const int warp = tid >> 5, lane = tid & 31;
  const int ks = blockIdx.y;
  const int kbeg = ks*KPB;
  const int rb0 = blockIdx.x*BR;          // block's first row
  const int rbase = rb0 + warp*4;         // this warp's 4 rows

  const uint32_t mb = s2u(smem);          // full[st] at mb + st*8

  if (tid == 0){ mbar_init(mb, NPROD); mbar_init(mb + 8, NPROD); }
  __syncthreads();

  auto issue = [&](int c){
    const int st = c & 1;
    const uint32_t m = mb + st*8;
    const int kc = kbeg + c*KCH;
    if (tid < BR){
      mbar_expect(m, KCH*4);
      const uint32_t wdst = s2u(smem + SM_W_OFF) + st*(BR*KCH*4) + tid*(KCH*4);
      bulk_g2s(wdst, W2 + (size_t)(rb0 + tid)*NN + kc, KCH*4, m);
    } else if (tid == BR){
      mbar_expect(m, KCH*16);
      bulk_g2s(s2u(smem + SM_CX_OFF) + st*(KCH*16), &g_Xa[(size_t)kc*4], KCH*16, m);
    } else if (tid == BR + 1){
      mbar_expect(m, KCH*16);
      bulk_g2s(s2u(smem + SM_CS_OFF) + st*(KCH*16), &g_Sa[(size_t)kc*4], KCH*16, m);
    }
  };

  issue(0); issue(1);

  ull acc[4][4];
  #pragma unroll
  for (int r = 0; r < 4; r++)
    #pragma unroll
    for (int j = 0; j < 4; j++) acc[r][j] = 0ull;

  for (int c = 0; c < NCH; c++){
    const int st = c & 1;
    mbar_wait(mb + st*8, (c >> 1) & 1);
    const float* w4 = (const float*)(smem + SM_W_OFF) + st*(BR*KCH) + warp*4*KCH;
    const float4* cx = (const float4*)(smem + SM_CX_OFF) + st*KCH;
    const float4* cs = (const float4*)(smem + SM_CS_OFF) + st*KCH;
    #pragma unroll
    for (int kk = 0; kk < KCH; kk += 64){
      const int k0 = kk + lane;
      const int k1 = k0 + 32;
      float w0[4], w1[4];
      #pragma unroll
      for (int r = 0; r < 4; r++){
        w0[r] = w4[r*KCH + k0];
        w1[r] = w4[r*KCH + k1];
      }
      {
        ulonglong2 vx = *(const ulonglong2*)&cx[k0];
        ulonglong2 vs = *(const ulonglong2*)&cs[k0];
        #pragma unroll
        for (int r = 0; r < 4; r++){
          ull wl = pk2(w0[r], w0[r]);
          acc[r][0] = fma2(wl, vx.x, acc[r][0]);
          acc[r][1] = fma2(wl, vx.y, acc[r][1]);
          acc[r][2] = fma2(wl, vs.x, acc[r][2]);
          acc[r][3] = fma2(wl, vs.y, acc[r][3]);
        }
      }
      {
        ulonglong2 vx = *(const ulonglong2*)&cx[k1];
        ulonglong2 vs = *(const ulonglong2*)&cs[k1];
        #pragma unroll
        for (int r = 0; r < 4; r++){
          ull wl = pk2(w1[r], w1[r]);
          acc[r][0] = fma2(wl, vx.x, acc[r][0]);
          acc[r][1] = fma2(wl, vx.y, acc[r][1]);
          acc[r][2] = fma2(wl, vs.x, acc[r][2]);
          acc[r][3] = fma2(wl, vs.y, acc[r][3]);
        }
      }
    }
    __syncthreads();
    if (c + NST < NCH) issue(c + NST);
  }

  #pragma unroll
  for (int r = 0; r < 4; r++){
    #pragma unroll
    for (int j = 0; j < 4; j++){
      ull v = acc[r][j];
      v = add2(v, __shfl_xor_sync(0xffffffffu, v, 16));
      v = add2(v, __shfl_xor_sync(0xffffffffu, v, 8));
      v = add2(v, __shfl_xor_sync(0xffffffffu, v, 4));
      v = add2(v, __shfl_xor_sync(0xffffffffu, v, 2));
      v = add2(v, __shfl_xor_sync(0xffffffffu, v, 1));
      if (lane == 0){
        float2 f = upk2(v);
        int row = rbase + r;
        if (j < 2){ g_MxP[ks][row*4 + 2*j]     = f.x; g_MxP[ks][row*4 + 2*j + 1]     = f.y; }
        else      { g_MsP[ks][row*4 + 2*(j-2)] = f.x; g_MsP[ks][row*4 + 2*(j-2) + 1] = f.y; }
      }
    }
  }
}

// ---------------- k5: gates + sinusoid + dual conv; sums split-K partials inline ----------------
__global__ void k5_conv(const float* __restrict__ X, const float* __restrict__ S,
                        const float* __restrict__ wx, const float* __restrict__ bx,
                        const float* __restrict__ ws, const float* __restrict__ bs,
                        float* __restrict__ out){
  __shared__ float in_s[2][8][258];
  __shared__ float wmid[2][8][8][3];
  __shared__ float bias[2][8];
  __shared__ float sins[258];
  const int t = threadIdx.x;
  const int n0 = blockIdx.x*256;

  for (int idx = t; idx < 384; idx += 256){
    int b = idx/192, rem = idx%192;
    int co = rem/24, ci = (rem%24)/3, kh = rem%3;
    const float* w = b ? ws : wx;
    wmid[b][co][ci][kh] = w[((co*8 + ci)*3 + kh)*3 + 1];
  }
  if (t < 16) bias[t>>3][t&7] = (t < 8) ? bx[t] : bs[t-8];
  for (int col = t; col < 258; col += 256)
    sins[col] = (float)sin((double)(n0 + col - 1));
  __syncthreads();

  for (int idx = t; idx < 2*8*258; idx += 256){
    int b = idx/(8*258); int rem = idx%(8*258);
    int ci = rem/258, col = rem%258;
    int n = n0 + col - 1;
    float v = 0.f;
    if (n >= 0 && n < NN){
      if (ci < 4){
        float m = 0.f;
        if (b == 0){
          #pragma unroll
          for (int ksp = 0; ksp < KSPL; ksp++) m += g_MxP[ksp][ci*NN + n];
        } else {
          #pragma unroll
          for (int ksp = 0; ksp < KSPL; ksp++) m += g_MsP[ksp][ci*NN + n];
        }
        v = m * X[ci*NN + n];
      } else {
        v = b ? S[(ci-4)*NN + n] : X[(ci-4)*NN + n];
      }
      if (b == 1) v += sins[col];
    }
    in_s[b][ci][col] = v;
  }
  __syncthreads();

  const int n = n0 + t;
  #pragma unroll
  for (int b = 0; b < 2; b++){
    #pragma unroll
    for (int co = 0; co < 8; co++){
      float a = bias[b][co];
      #pragma unroll
      for (int ci = 0; ci < 8; ci++){
        a = fmaf(wmid[b][co][ci][0], in_s[b][ci][t  ], a);
        a = fmaf(wmid[b][co][ci][1], in_s[b][ci][t+1], a);
        a = fmaf(wmid[b][co][ci][2], in_s[b][ci][t+2], a);
      }
      out[(size_t)b*8*NN + (size_t)co*NN + n] = a;
    }
  }
}

// ---------------- launch ----------------
extern "C" void kernel_launch(void* const* d_in, const int* in_sizes, int n_in,
                              void* d_out, int out_size){
  (void)in_sizes; (void)n_in; (void)out_size;
  const float* X   = (const float*)d_in[0];
  const float* S   = (const float*)d_in[1];
  const float* W1x = (const float*)d_in[2];
  const float* W1s = (const float*)d_in[3];
  const float* W2  = (const float*)d_in[4];
  const float* cwx = (const float*)d_in[5];
  const float* cbx = (const float*)d_in[6];
  const float* cws = (const float*)d_in[7];
  const float* cbs = (const float*)d_in[8];
  float* out = (float*)d_out;

  static int smem_set = 0;
  if (!smem_set){
    cudaFuncSetAttribute(k4_gemv, cudaFuncAttributeMaxDynamicSharedMemorySize, SM_TOTAL);
    smem_set = 1;
  }

  k1_embed  <<<NB1, 256>>>(X, S, W1x, W1s);
  k1b_nmax  <<<1, 32>>>();
  k2_attn   <<<dim3(JBLK, IBLK, 2), 256>>>();
  k3_combine<<<512, 256>>>();
  k4_gemv   <<<dim3(NN/BR, KSPL), 256, SM_TOTAL>>>(W2);
  k5_conv   <<<NN/256, 256>>>(X, S, cwx, cbx, cws, cbs, out);
}

// round 16
// speedup vs baseline: 1.0786x; 1.0093x over previous
#include <cuda_runtime.h>
#include <cmath>
#include <cstdint>

#define NN 8192
#define NB1 32
#define IBLK 32
#define ICH (NN/IBLK)      /* 256 */
#define JBLK 16
#define JPB (NN/JBLK)      /* 512  */

/* ---- k4 TMA config (proven: KCH256/NST2, distributed issue) ---- */
#define BR 32
#define KCH 256
#define NST 2
#define KSPL 4
#define KPB (NN/KSPL)      /* 2048 */
#define NCH (KPB/KCH)      /* 8 */
#define SM_W_OFF 128
#define SM_W_SZ  (NST*BR*KCH*4)
#define SM_CX_OFF (SM_W_OFF + SM_W_SZ)
#define SM_CS_OFF (SM_CX_OFF + NST*KCH*16)
#define SM_TOTAL  (SM_CS_OFF + NST*KCH*16)
#define NPROD (BR + 2)

typedef unsigned long long ull;

// ---------------- scratch ----------------
__device__ __align__(16) float4 g_XeT[NN];
__device__ __align__(16) float4 g_SeT[NN];
__device__ float g_bmax[NB1];
__device__ float g_nmax;
__device__ int   g_k1ctr;
__device__ __align__(16) float4 g_pnum[2][IBLK][NN];
__device__ float g_pden[2][IBLK][NN];
__device__ __align__(16) float g_Xa[4*NN];
__device__ __align__(16) float g_Sa[4*NN];
__device__ __align__(16) float g_MxP[KSPL][4*NN];
__device__ __align__(16) float g_MsP[KSPL][4*NN];

// ---------------- helpers ----------------
__device__ __forceinline__ ull pk2(float lo, float hi){ ull r; asm("mov.b64 %0, {%1, %2};" : "=l"(r) : "f"(lo), "f"(hi)); return r; }
__device__ __forceinline__ float2 upk2(ull v){ float2 f; asm("mov.b64 {%0, %1}, %2;" : "=f"(f.x), "=f"(f.y) : "l"(v)); return f; }
__device__ __forceinline__ ull fma2(ull a, ull b, ull c){ ull d; asm("fma.rn.f32x2 %0, %1, %2, %3;" : "=l"(d) : "l"(a), "l"(b), "l"(c)); return d; }
__device__ __forceinline__ ull add2(ull a, ull b){ ull d; asm("add.rn.f32x2 %0, %1, %2;" : "=l"(d) : "l"(a), "l"(b)); return d; }
__device__ __forceinline__ ull ex2pair(ull g){
  ull e;
  asm("{\n\t.reg .f32 lo, hi;\n\t"
      "mov.b64 {lo, hi}, %1;\n\t"
      "ex2.approx.ftz.f32 lo, lo;\n\t"
      "ex2.approx.ftz.f32 hi, hi;\n\t"
      "mov.b64 %0, {lo, hi};\n\t}" : "=l"(e) : "l"(g));
  return e;
}
__device__ __forceinline__ uint32_t s2u(const void* p){
  uint32_t a; asm("{ .reg .u64 t; cvta.to.shared.u64 t, %1; cvt.u32.u64 %0, t; }" : "=r"(a) : "l"(p)); return a;
}
__device__ __forceinline__ void mbar_init(uint32_t m, uint32_t cnt){
  asm volatile("mbarrier.init.shared.b64 [%0], %1;" :: "r"(m), "r"(cnt) : "memory");
}
__device__ __forceinline__ void mbar_expect(uint32_t m, uint32_t bytes){
  asm volatile("mbarrier.arrive.expect_tx.shared.b64 _, [%0], %1;" :: "r"(m), "r"(bytes) : "memory");
}
__device__ __forceinline__ void mbar_wait(uint32_t m, uint32_t ph){
  uint32_t done;
  asm volatile("{\n\t.reg .pred p;\n\t"
    "mbarrier.try_wait.parity.acquire.cta.shared::cta.b64 p, [%1], %2;\n\t"
    "selp.b32 %0, 1, 0, p;\n\t}" : "=r"(done) : "r"(m), "r"(ph) : "memory");
  while(!done){
    asm volatile("{\n\t.reg .pred p;\n\t"
      "mbarrier.try_wait.parity.acquire.cta.shared::cta.b64 p, [%1], %2, 0x989680;\n\t"
      "selp.b32 %0, 1, 0, p;\n\t}" : "=r"(done) : "r"(m), "r"(ph) : "memory");
  }
}
__device__ __forceinline__ void bulk_g2s(uint32_t sdst, const void* gsrc, uint32_t bytes, uint32_t m){
  unsigned long long g;
  asm("cvta.to.global.u64 %0, %1;" : "=l"(g) : "l"(gsrc));
  asm volatile("cp.async.bulk.shared::cluster.global.mbarrier::complete_tx::bytes [%0], [%1], %2, [%3];"
    :: "r"(sdst), "l"(g), "r"(bytes), "r"(m) : "memory");
}

// ---------------- k1: embeds + fused global max (last-block finisher) ----------------
__global__ void k1_embed(const float* __restrict__ X, const float* __restrict__ S,
                         const float* __restrict__ W1x, const float* __restrict__ W1s){
  int j = blockIdx.x*blockDim.x + threadIdx.x;
  float s0=S[j], s1=S[NN+j], s2=S[2*NN+j], s3=S[3*NN+j];
  float x0=X[j], x1=X[NN+j], x2=X[2*NN+j], x3=X[3*NN+j];
  float4 xe, se;
  xe.x = W1x[ 0]*s0 + W1x[ 1]*s1 + W1x[ 2]*s2 + W1x[ 3]*s3;
  xe.y = W1x[ 4]*s0 + W1x[ 5]*s1 + W1x[ 6]*s2 + W1x[ 7]*s3;
  xe.z = W1x[ 8]*s0 + W1x[ 9]*s1 + W1x[10]*s2 + W1x[11]*s3;
  xe.w = W1x[12]*s0 + W1x[13]*s1 + W1x[14]*s2 + W1x[15]*s3;
  se.x = W1s[ 0]*x0 + W1s[ 1]*x1 + W1s[ 2]*x2 + W1s[ 3]*x3;
  se.y = W1s[ 4]*x0 + W1s[ 5]*x1 + W1s[ 6]*x2 + W1s[ 7]*x3;
  se.z = W1s[ 8]*x0 + W1s[ 9]*x1 + W1s[10]*x2 + W1s[11]*x3;
  se.w = W1s[12]*x0 + W1s[13]*x1 + W1s[14]*x2 + W1s[15]*x3;
  g_XeT[j] = xe; g_SeT[j] = se;
  float nx = xe.x*xe.x + xe.y*xe.y + xe.z*xe.z + xe.w*xe.w;
  float ns = se.x*se.x + se.y*se.y + se.z*se.z + se.w*se.w;
  float m = sqrtf(fmaxf(nx, ns));
  __shared__ float red[256];
  red[threadIdx.x] = m; __syncthreads();
  for (int s = 128; s > 0; s >>= 1){
    if (threadIdx.x < s) red[threadIdx.x] = fmaxf(red[threadIdx.x], red[threadIdx.x+s]);
    __syncthreads();
  }
  if (threadIdx.x == 0){
    g_bmax[blockIdx.x] = red[0];
    __threadfence();
    int done = atomicAdd(&g_k1ctr, 1);
    red[0] = (done == NB1-1) ? 1.0f : 0.0f;
  }
  __syncthreads();
  if (red[0] != 0.0f && threadIdx.x < 32){
    float mm = g_bmax[threadIdx.x];
    #pragma unroll
    for (int s = 16; s > 0; s >>= 1) mm = fmaxf(mm, __shfl_xor_sync(0xffffffffu, mm, s));
    if (threadIdx.x == 0){ g_nmax = mm; g_k1ctr = 0; }
  }
}

// ---------------- k2: rank-4 streaming attention; 4 j/thread, 128-thread blocks ----------------
__global__ void __launch_bounds__(128, 4) k2_attn(){
  const int jb = blockIdx.x, ib = blockIdx.y, br = blockIdx.z;
  const float4* __restrict__ E = br ? g_SeT : g_XeT;
  __shared__ float shX[ICH], shY[ICH], shZ[ICH], shW[ICH];

  const float Nmax = g_nmax;
  const int ibase = ib*ICH;
  for (int t = threadIdx.x; t < ICH; t += 128){
    float4 v = E[ibase + t];
    shX[t]=v.x; shY[t]=v.y; shZ[t]=v.z; shW[t]=v.w;
  }
  __syncthreads();

  const float L2E = 1.4426950408889634f;
  ull qx[4], qy[4], qz[4], qw[4], cc[4];
  ull dn[4], ax[4], ay[4], az[4], aw[4];
  #pragma unroll
  for (int u = 0; u < 4; u++){
    int j = jb*JPB + u*128 + threadIdx.x;
    float4 q = E[j];
    float c = sqrtf(q.x*q.x+q.y*q.y+q.z*q.z+q.w*q.w) * Nmax * L2E;
    qx[u] = pk2(q.x*L2E, q.x*L2E); qy[u] = pk2(q.y*L2E, q.y*L2E);
    qz[u] = pk2(q.z*L2E, q.z*L2E); qw[u] = pk2(q.w*L2E, q.w*L2E);
    cc[u] = pk2(-c, -c);
    dn[u]=0ull; ax[u]=0ull; ay[u]=0ull; az[u]=0ull; aw[u]=0ull;
  }

  const ull* sX = (const ull*)shX; const ull* sY = (const ull*)shY;
  const ull* sZ = (const ull*)shZ; const ull* sW = (const ull*)shW;

  #pragma unroll 4
  for (int ii = 0; ii < ICH/2; ii++){
    ull sx = sX[ii], sy = sY[ii], sz = sZ[ii], sw = sW[ii];
    #pragma unroll
    for (int u = 0; u < 4; u++){
      ull g = fma2(qx[u], sx, fma2(qy[u], sy, fma2(qz[u], sz, fma2(qw[u], sw, cc[u]))));
      ull e = ex2pair(g);
      dn[u] = add2(dn[u], e);
      ax[u] = fma2(sx, e, ax[u]); ay[u] = fma2(sy, e, ay[u]);
      az[u] = fma2(sz, e, az[u]); aw[u] = fma2(sw, e, aw[u]);
    }
  }

  #pragma unroll
  for (int u = 0; u < 4; u++){
    int j = jb*JPB + u*128 + threadIdx.x;
    float2 t2; float4 p;
    t2 = upk2(ax[u]); p.x = t2.x + t2.y;
    t2 = upk2(ay[u]); p.y = t2.x + t2.y;
    t2 = upk2(az[u]); p.z = t2.x + t2.y;
    t2 = upk2(aw[u]); p.w = t2.x + t2.y;
    g_pnum[br][ib][j] = p;
    t2 = upk2(dn[u]); g_pden[br][ib][j] = t2.x + t2.y;
  }
}

// ---------------- k3: combine partials (coalesced, 2 j/thread, 256 blocks) ----------------
__global__ void k3_combine(){
  __shared__ float4 s_n[8][64];
  __shared__ float  s_d[8][64];
  const int bid  = blockIdx.x;          // 0..255
  const int br   = bid >> 7;
  const int lane = threadIdx.x & 31;
  const int q    = threadIdx.x >> 5;    // 0..7
  const int jbase = (bid & 127)*64;
  const int j  = jbase + lane;
  const int j2 = j + 32;
  float4 n = make_float4(0.f,0.f,0.f,0.f), m = make_float4(0.f,0.f,0.f,0.f);
  float d = 0.f, e = 0.f;
  #pragma unroll
  for (int i = 0; i < IBLK/8; i++){
    int ib = q*(IBLK/8) + i;
    float4 p  = g_pnum[br][ib][j];
    float4 p2 = g_pnum[br][ib][j2];
    n.x += p.x;  n.y += p.y;  n.z += p.z;  n.w += p.w;
    m.x += p2.x; m.y += p2.y; m.z += p2.z; m.w += p2.w;
    d += g_pden[br][ib][j];
    e += g_pden[br][ib][j2];
  }
  s_n[q][lane] = n;      s_d[q][lane] = d;
  s_n[q][lane+32] = m;   s_d[q][lane+32] = e;
  __syncthreads();
  if (q < 2){
    const int jj = q*32 + lane;
    float4 a = s_n[0][jj]; float dd = s_d[0][jj];
    #pragma unroll
    for (int k = 1; k < 8; k++){
      float4 p = s_n[k][jj];
      a.x += p.x; a.y += p.y; a.z += p.z; a.w += p.w;
      dd += s_d[k][jj];
    }
    float inv = 1.0f / dd;
    int jo = jbase + jj;
    float* out = br ? g_Sa : g_Xa;
    out[0*NN+jo] = a.x*inv; out[1*NN+jo] = a.y*inv;
    out[2*NN+jo] = a.z*inv; out[3*NN+jo] = a.w*inv;
  }
}

// ---------------- k4: M = W2 @ C; TMA-1D pipeline, split-K x4, distributed issue ----------------
__global__ void __launch_bounds__(256, 2) k4_gemv(const float* __restrict__ W2){
  extern __shared__ __align__(16) char smem[];
  const int tid = threadIdx.x;
  const int warp = tid >> 5, lane = tid & 31;
  const int ks = blockIdx.y;
  const int kbeg = ks*KPB;
  const int rb0 = blockIdx.x*BR;
  const int rbase = rb0 + warp*4;

  const uint32_t mb = s2u(smem);

  if (tid == 0){ mbar_init(mb, NPROD); mbar_init(mb + 8, NPROD); }
  __syncthreads();

  auto issue = [&](int c){
    const int st = c & 1;
    const uint32_t m = mb + st*8;
    const int kc = kbeg + c*KCH;
    if (tid < BR){
      mbar_expect(m, KCH*4);
      const uint32_t wdst = s2u(smem + SM_W_OFF) + st*(BR*KCH*4) + tid*(KCH*4);
      bulk_g2s(wdst, W2 + (size_t)(rb0 + tid)*NN + kc, KCH*4, m);
    } else if (tid == BR){
      mbar_expect(m, KCH*16);
      bulk_g2s(s2u(smem + SM_CX_OFF) + st*(KCH*16), &g_Xa[(size_t)kc*4], KCH*16, m);
    } else if (tid == BR + 1){
      mbar_expect(m, KCH*16);
      bulk_g2s(s2u(smem + SM_CS_OFF) + st*(KCH*16), &g_Sa[(size_t)kc*4], KCH*16, m);
    }
  };

  issue(0); issue(1);

  ull acc[4][4];
  #pragma unroll
  for (int r = 0; r < 4; r++)
    #pragma unroll
    for (int j = 0; j < 4; j++) acc[r][j] = 0ull;

  for (int c = 0; c < NCH; c++){
    const int st = c & 1;
    mbar_wait(mb + st*8, (c >> 1) & 1);
    const float* w4 = (const float*)(smem + SM_W_OFF) + st*(BR*KCH) + warp*4*KCH;
    const float4* cx = (const float4*)(smem + SM_CX_OFF) + st*KCH;
    const float4* cs = (const float4*)(smem + SM_CS_OFF) + st*KCH;
    #pragma unroll
    for (int kk = 0; kk < KCH; kk += 64){
      const int k0 = kk + lane;
      const int k1 = k0 + 32;
      float w0[4], w1[4];
      #pragma unroll
      for (int r = 0; r < 4; r++){
        w0[r] = w4[r*KCH + k0];
        w1[r] = w4[r*KCH + k1];
      }
      {
        ulonglong2 vx = *(const ulonglong2*)&cx[k0];
        ulonglong2 vs = *(const ulonglong2*)&cs[k0];
        #pragma unroll
        for (int r = 0; r < 4; r++){
          ull wl = pk2(w0[r], w0[r]);
          acc[r][0] = fma2(wl, vx.x, acc[r][0]);
          acc[r][1] = fma2(wl, vx.y, acc[r][1]);
          acc[r][2] = fma2(wl, vs.x, acc[r][2]);
          acc[r][3] = fma2(wl, vs.y, acc[r][3]);
        }
      }
      {
        ulonglong2 vx = *(const ulonglong2*)&cx[k1];
        ulonglong2 vs = *(const ulonglong2*)&cs[k1];
        #pragma unroll
        for (int r = 0; r < 4; r++){
          ull wl = pk2(w1[r], w1[r]);
          acc[r][0] = fma2(wl, vx.x, acc[r][0]);
          acc[r][1] = fma2(wl, vx.y, acc[r][1]);
          acc[r][2] = fma2(wl, vs.x, acc[r][2]);
          acc[r][3] = fma2(wl, vs.y, acc[r][3]);
        }
      }
    }
    __syncthreads();
    if (c + NST < NCH) issue(c + NST);
  }

  #pragma unroll
  for (int r = 0; r < 4; r++){
    #pragma unroll
    for (int j = 0; j < 4; j++){
      ull v = acc[r][j];
      v = add2(v, __shfl_xor_sync(0xffffffffu, v, 16));
      v = add2(v, __shfl_xor_sync(0xffffffffu, v, 8));
      v = add2(v, __shfl_xor_sync(0xffffffffu, v, 4));
      v = add2(v, __shfl_xor_sync(0xffffffffu, v, 2));
      v = add2(v, __shfl_xor_sync(0xffffffffu, v, 1));
      if (lane == 0){
        float2 f = upk2(v);
        int row = rbase + r;
        if (j < 2){ g_MxP[ks][row*4 + 2*j]     = f.x; g_MxP[ks][row*4 + 2*j + 1]     = f.y; }
        else      { g_MsP[ks][row*4 + 2*(j-2)] = f.x; g_MsP[ks][row*4 + 2*(j-2) + 1] = f.y; }
      }
    }
  }
}

// ---------------- k5: gates + sinusoid + dual conv; sums split-K partials inline ----------------
__global__ void k5_conv(const float* __restrict__ X, const float* __restrict__ S,
                        const float* __restrict__ wx, const float* __restrict__ bx,
                        const float* __restrict__ ws, const float* __restrict__ bs,
                        float* __restrict__ out){
  __shared__ float in_s[2][8][258];
  __shared__ float wmid[2][8][8][3];
  __shared__ float bias[2][8];
  __shared__ float sins[258];
  const int t = threadIdx.x;
  const int n0 = blockIdx.x*256;

  for (int idx = t; idx < 384; idx += 256){
    int b = idx/192, rem = idx%192;
    int co = rem/24, ci = (rem%24)/3, kh = rem%3;
    const float* w = b ? ws : wx;
    wmid[b][co][ci][kh] = w[((co*8 + ci)*3 + kh)*3 + 1];
  }
  if (t < 16) bias[t>>3][t&7] = (t < 8) ? bx[t] : bs[t-8];
  for (int col = t; col < 258; col += 256)
    sins[col] = (float)sin((double)(n0 + col - 1));
  __syncthreads();

  for (int idx = t; idx < 2*8*258; idx += 256){
    int b = idx/(8*258); int rem = idx%(8*258);
    int ci = rem/258, col = rem%258;
    int n = n0 + col - 1;
    float v = 0.f;
    if (n >= 0 && n < NN){
      if (ci < 4){
        float m = 0.f;
        if (b == 0){
          #pragma unroll
          for (int ksp = 0; ksp < KSPL; ksp++) m += g_MxP[ksp][ci*NN + n];
        } else {
          #pragma unroll
          for (int ksp = 0; ksp < KSPL; ksp++) m += g_MsP[ksp][ci*NN + n];
        }
        v = m * X[ci*NN + n];
      } else {
        v = b ? S[(ci-4)*NN + n] : X[(ci-4)*NN + n];
      }
      if (b == 1) v += sins[col];
    }
    in_s[b][ci][col] = v;
  }
  __syncthreads();

  const int n = n0 + t;
  #pragma unroll
  for (int b = 0; b < 2; b++){
    #pragma unroll
    for (int co = 0; co < 8; co++){
      float a = bias[b][co];
      #pragma unroll
      for (int ci = 0; ci < 8; ci++){
        a = fmaf(wmid[b][co][ci][0], in_s[b][ci][t  ], a);
        a = fmaf(wmid[b][co][ci][1], in_s[b][ci][t+1], a);
        a = fmaf(wmid[b][co][ci][2], in_s[b][ci][t+2], a);
      }
      out[(size_t)b*8*NN + (size_t)co*NN + n] = a;
    }
  }
}

// ---------------- launch ----------------
extern "C" void kernel_launch(void* const* d_in, const int* in_sizes, int n_in,
                              void* d_out, int out_size){
  (void)in_sizes; (void)n_in; (void)out_size;
  const float* X   = (const float*)d_in[0];
  const float* S   = (const float*)d_in[1];
  const float* W1x = (const float*)d_in[2];
  const float* W1s = (const float*)d_in[3];
  const float* W2  = (const float*)d_in[4];
  const float* cwx = (const float*)d_in[5];
  const float* cbx = (const float*)d_in[6];
  const float* cws = (const float*)d_in[7];
  const float* cbs = (const float*)d_in[8];
  float* out = (float*)d_out;

  static int smem_set = 0;
  if (!smem_set){
    cudaFuncSetAttribute(k4_gemv, cudaFuncAttributeMaxDynamicSharedMemorySize, SM_TOTAL);
    smem_set = 1;
  }

  k1_embed  <<<NB1, 256>>>(X, S, W1x, W1s);
  k2_attn   <<<dim3(JBLK, IBLK, 2), 128>>>();
  k3_combine<<<256, 256>>>();
  k4_gemv   <<<dim3(NN/BR, KSPL), 256, SM_TOTAL>>>(W2);
  k5_conv   <<<NN/256, 256>>>(X, S, cwx, cbx, cws, cbs, out);
}

// round 17
// speedup vs baseline: 1.1120x; 1.0310x over previous
#include <cuda_runtime.h>
#include <cmath>
#include <cstdint>

#define NN 8192
#define NB1 32
#define IBLK 32
#define ICH (NN/IBLK)      /* 256 */
#define JBLK 16
#define JPB (NN/JBLK)      /* 512  */

/* ---- k4 TMA config: persistent, KCH256/NST2 ring, split-K x8 ---- */
#define BR 32
#define KCH 256
#define NST 2
#define KSPL 8
#define KPB (NN/KSPL)      /* 1024 */
#define NCH (KPB/KCH)      /* 4 chunks per tile */
#define NTILES (256*KSPL)  /* 2048 */
#define GRID4 296
#define SM_W_OFF 128
#define SM_W_SZ  (NST*BR*KCH*4)
#define SM_CX_OFF (SM_W_OFF + SM_W_SZ)
#define SM_CS_OFF (SM_CX_OFF + NST*KCH*16)
#define SM_TOTAL  (SM_CS_OFF + NST*KCH*16)
#define NPROD (BR + 2)

typedef unsigned long long ull;

// ---------------- scratch ----------------
__device__ __align__(16) float4 g_XeT[NN];
__device__ __align__(16) float4 g_SeT[NN];
__device__ float g_bmax[NB1];
__device__ float g_nmax;
__device__ int   g_k1ctr;
__device__ __align__(16) float4 g_pnum[2][IBLK][NN];
__device__ float g_pden[2][IBLK][NN];
__device__ __align__(16) float g_Xa[4*NN];
__device__ __align__(16) float g_Sa[4*NN];
__device__ __align__(16) float g_MxP[KSPL][4*NN];
__device__ __align__(16) float g_MsP[KSPL][4*NN];

// ---------------- helpers ----------------
__device__ __forceinline__ ull pk2(float lo, float hi){ ull r; asm("mov.b64 %0, {%1, %2};" : "=l"(r) : "f"(lo), "f"(hi)); return r; }
__device__ __forceinline__ float2 upk2(ull v){ float2 f; asm("mov.b64 {%0, %1}, %2;" : "=f"(f.x), "=f"(f.y) : "l"(v)); return f; }
__device__ __forceinline__ ull fma2(ull a, ull b, ull c){ ull d; asm("fma.rn.f32x2 %0, %1, %2, %3;" : "=l"(d) : "l"(a), "l"(b), "l"(c)); return d; }
__device__ __forceinline__ ull add2(ull a, ull b){ ull d; asm("add.rn.f32x2 %0, %1, %2;" : "=l"(d) : "l"(a), "l"(b)); return d; }
__device__ __forceinline__ ull ex2pair(ull g){
  ull e;
  asm("{\n\t.reg .f32 lo, hi;\n\t"
      "mov.b64 {lo, hi}, %1;\n\t"
      "ex2.approx.ftz.f32 lo, lo;\n\t"
      "ex2.approx.ftz.f32 hi, hi;\n\t"
      "mov.b64 %0, {lo, hi};\n\t}" : "=l"(e) : "l"(g));
  return e;
}
__device__ __forceinline__ uint32_t s2u(const void* p){
  uint32_t a; asm("{ .reg .u64 t; cvta.to.shared.u64 t, %1; cvt.u32.u64 %0, t; }" : "=r"(a) : "l"(p)); return a;
}
__device__ __forceinline__ void mbar_init(uint32_t m, uint32_t cnt){
  asm volatile("mbarrier.init.shared.b64 [%0], %1;" :: "r"(m), "r"(cnt) : "memory");
}
__device__ __forceinline__ void mbar_expect(uint32_t m, uint32_t bytes){
  asm volatile("mbarrier.arrive.expect_tx.shared.b64 _, [%0], %1;" :: "r"(m), "r"(bytes) : "memory");
}
__device__ __forceinline__ void mbar_wait(uint32_t m, uint32_t ph){
  uint32_t done;
  asm volatile("{\n\t.reg .pred p;\n\t"
    "mbarrier.try_wait.parity.acquire.cta.shared::cta.b64 p, [%1], %2;\n\t"
    "selp.b32 %0, 1, 0, p;\n\t}" : "=r"(done) : "r"(m), "r"(ph) : "memory");
  while(!done){
    asm volatile("{\n\t.reg .pred p;\n\t"
      "mbarrier.try_wait.parity.acquire.cta.shared::cta.b64 p, [%1], %2, 0x989680;\n\t"
      "selp.b32 %0, 1, 0, p;\n\t}" : "=r"(done) : "r"(m), "r"(ph) : "memory");
  }
}
__device__ __forceinline__ void bulk_g2s(uint32_t sdst, const void* gsrc, uint32_t bytes, uint32_t m){
  unsigned long long g;
  asm("cvta.to.global.u64 %0, %1;" : "=l"(g) : "l"(gsrc));
  asm volatile("cp.async.bulk.shared::cluster.global.mbarrier::complete_tx::bytes [%0], [%1], %2, [%3];"
    :: "r"(sdst), "l"(g), "r"(bytes), "r"(m) : "memory");
}

// ---------------- k1: embeds + fused global max (last-block finisher) ----------------
__global__ void k1_embed(const float* __restrict__ X, const float* __restrict__ S,
                         const float* __restrict__ W1x, const float* __restrict__ W1s){
  int j = blockIdx.x*blockDim.x + threadIdx.x;
  float s0=S[j], s1=S[NN+j], s2=S[2*NN+j], s3=S[3*NN+j];
  float x0=X[j], x1=X[NN+j], x2=X[2*NN+j], x3=X[3*NN+j];
  float4 xe, se;
  xe.x = W1x[ 0]*s0 + W1x[ 1]*s1 + W1x[ 2]*s2 + W1x[ 3]*s3;
  xe.y = W1x[ 4]*s0 + W1x[ 5]*s1 + W1x[ 6]*s2 + W1x[ 7]*s3;
  xe.z = W1x[ 8]*s0 + W1x[ 9]*s1 + W1x[10]*s2 + W1x[11]*s3;
  xe.w = W1x[12]*s0 + W1x[13]*s1 + W1x[14]*s2 + W1x[15]*s3;
  se.x = W1s[ 0]*x0 + W1s[ 1]*x1 + W1s[ 2]*x2 + W1s[ 3]*x3;
  se.y = W1s[ 4]*x0 + W1s[ 5]*x1 + W1s[ 6]*x2 + W1s[ 7]*x3;
  se.z = W1s[ 8]*x0 + W1s[ 9]*x1 + W1s[10]*x2 + W1s[11]*x3;
  se.w = W1s[12]*x0 + W1s[13]*x1 + W1s[14]*x2 + W1s[15]*x3;
  g_XeT[j] = xe; g_SeT[j] = se;
  float nx = xe.x*xe.x + xe.y*xe.y + xe.z*xe.z + xe.w*xe.w;
  float ns = se.x*se.x + se.y*se.y + se.z*se.z + se.w*se.w;
  float m = sqrtf(fmaxf(nx, ns));
  __shared__ float red[256];
  red[threadIdx.x] = m; __syncthreads();
  for (int s = 128; s > 0; s >>= 1){
    if (threadIdx.x < s) red[threadIdx.x] = fmaxf(red[threadIdx.x], red[threadIdx.x+s]);
    __syncthreads();
  }
  if (threadIdx.x == 0){
    g_bmax[blockIdx.x] = red[0];
    __threadfence();
    int done = atomicAdd(&g_k1ctr, 1);
    red[0] = (done == NB1-1) ? 1.0f : 0.0f;
  }
  __syncthreads();
  if (red[0] != 0.0f && threadIdx.x < 32){
    float mm = g_bmax[threadIdx.x];
    #pragma unroll
    for (int s = 16; s > 0; s >>= 1) mm = fmaxf(mm, __shfl_xor_sync(0xffffffffu, mm, s));
    if (threadIdx.x == 0){ g_nmax = mm; g_k1ctr = 0; }
  }
}

// ---------------- k2: rank-4 streaming attention; 4 j/thread, 128-thread blocks ----------------
__global__ void __launch_bounds__(128, 4) k2_attn(){
  const int jb = blockIdx.x, ib = blockIdx.y, br = blockIdx.z;
  const float4* __restrict__ E = br ? g_SeT : g_XeT;
  __shared__ float shX[ICH], shY[ICH], shZ[ICH], shW[ICH];

  const float Nmax = g_nmax;
  const int ibase = ib*ICH;
  for (int t = threadIdx.x; t < ICH; t += 128){
    float4 v = E[ibase + t];
    shX[t]=v.x; shY[t]=v.y; shZ[t]=v.z; shW[t]=v.w;
  }
  __syncthreads();

  const float L2E = 1.4426950408889634f;
  ull qx[4], qy[4], qz[4], qw[4], cc[4];
  ull dn[4], ax[4], ay[4], az[4], aw[4];
  #pragma unroll
  for (int u = 0; u < 4; u++){
    int j = jb*JPB + u*128 + threadIdx.x;
    float4 q = E[j];
    float c = sqrtf(q.x*q.x+q.y*q.y+q.z*q.z+q.w*q.w) * Nmax * L2E;
    qx[u] = pk2(q.x*L2E, q.x*L2E); qy[u] = pk2(q.y*L2E, q.y*L2E);
    qz[u] = pk2(q.z*L2E, q.z*L2E); qw[u] = pk2(q.w*L2E, q.w*L2E);
    cc[u] = pk2(-c, -c);
    dn[u]=0ull; ax[u]=0ull; ay[u]=0ull; az[u]=0ull; aw[u]=0ull;
  }

  const ull* sX = (const ull*)shX; const ull* sY = (const ull*)shY;
  const ull* sZ = (const ull*)shZ; const ull* sW = (const ull*)shW;

  #pragma unroll 4
  for (int ii = 0; ii < ICH/2; ii++){
    ull sx = sX[ii], sy = sY[ii], sz = sZ[ii], sw = sW[ii];
    #pragma unroll
    for (int u = 0; u < 4; u++){
      ull g = fma2(qx[u], sx, fma2(qy[u], sy, fma2(qz[u], sz, fma2(qw[u], sw, cc[u]))));
      ull e = ex2pair(g);
      dn[u] = add2(dn[u], e);
      ax[u] = fma2(sx, e, ax[u]); ay[u] = fma2(sy, e, ay[u]);
      az[u] = fma2(sz, e, az[u]); aw[u] = fma2(sw, e, aw[u]);
    }
  }

  #pragma unroll
  for (int u = 0; u < 4; u++){
    int j = jb*JPB + u*128 + threadIdx.x;
    float2 t2; float4 p;
    t2 = upk2(ax[u]); p.x = t2.x + t2.y;
    t2 = upk2(ay[u]); p.y = t2.x + t2.y;
    t2 = upk2(az[u]); p.z = t2.x + t2.y;
    t2 = upk2(aw[u]); p.w = t2.x + t2.y;
    g_pnum[br][ib][j] = p;
    t2 = upk2(dn[u]); g_pden[br][ib][j] = t2.x + t2.y;
  }
}

// ---------------- k3: combine partials (coalesced, 2 j/thread, 256 blocks) ----------------
__global__ void k3_combine(){
  __shared__ float4 s_n[8][64];
  __shared__ float  s_d[8][64];
  const int bid  = blockIdx.x;          // 0..255
  const int br   = bid >> 7;
  const int lane = threadIdx.x & 31;
  const int q    = threadIdx.x >> 5;    // 0..7
  const int jbase = (bid & 127)*64;
  const int j  = jbase + lane;
  const int j2 = j + 32;
  float4 n = make_float4(0.f,0.f,0.f,0.f), m = make_float4(0.f,0.f,0.f,0.f);
  float d = 0.f, e = 0.f;
  #pragma unroll
  for (int i = 0; i < IBLK/8; i++){
    int ib = q*(IBLK/8) + i;
    float4 p  = g_pnum[br][ib][j];
    float4 p2 = g_pnum[br][ib][j2];
    n.x += p.x;  n.y += p.y;  n.z += p.z;  n.w += p.w;
    m.x += p2.x; m.y += p2.y; m.z += p2.z; m.w += p2.w;
    d += g_pden[br][ib][j];
    e += g_pden[br][ib][j2];
  }
  s_n[q][lane] = n;      s_d[q][lane] = d;
  s_n[q][lane+32] = m;   s_d[q][lane+32] = e;
  __syncthreads();
  if (q < 2){
    const int jj = q*32 + lane;
    float4 a = s_n[0][jj]; float dd = s_d[0][jj];
    #pragma unroll
    for (int k = 1; k < 8; k++){
      float4 p = s_n[k][jj];
      a.x += p.x; a.y += p.y; a.z += p.z; a.w += p.w;
      dd += s_d[k][jj];
    }
    float inv = 1.0f / dd;
    int jo = jbase + jj;
    float* out = br ? g_Sa : g_Xa;
    out[0*NN+jo] = a.x*inv; out[1*NN+jo] = a.y*inv;
    out[2*NN+jo] = a.z*inv; out[3*NN+jo] = a.w*inv;
  }
}

// ---------------- k4: PERSISTENT M = W2 @ C; TMA ring runs continuously across tiles ----------------
__global__ void __launch_bounds__(256, 2) k4_gemv(const float* __restrict__ W2){
  extern __shared__ __align__(16) char smem[];
  const int tid = threadIdx.x;
  const int warp = tid >> 5, lane = tid & 31;
  const int bid = blockIdx.x;

  const uint32_t mb = s2u(smem);
  if (tid == 0){ mbar_init(mb, NPROD); mbar_init(mb + 8, NPROD); }
  __syncthreads();

  const int ntile = (NTILES - bid + GRID4 - 1) / GRID4;
  const int total = ntile * NCH;

  // issue chunk #seq of this block's sequential chunk list
  auto issue = [&](int seq){
    const int tIdx = seq >> 2;            // NCH = 4
    const int c    = seq & 3;
    const int g    = bid + tIdx*GRID4;    // global tile id
    const int rb0  = (g & 255)*BR;
    const int ks   = g >> 8;
    const int kc   = ks*KPB + c*KCH;
    const int st   = seq & 1;
    const uint32_t m = mb + st*8;
    if (tid < BR){
      mbar_expect(m, KCH*4);
      const uint32_t wdst = s2u(smem + SM_W_OFF) + st*(BR*KCH*4) + tid*(KCH*4);
      bulk_g2s(wdst, W2 + (size_t)(rb0 + tid)*NN + kc, KCH*4, m);
    } else if (tid == BR){
      mbar_expect(m, KCH*16);
      bulk_g2s(s2u(smem + SM_CX_OFF) + st*(KCH*16), &g_Xa[(size_t)kc*4], KCH*16, m);
    } else if (tid == BR + 1){
      mbar_expect(m, KCH*16);
      bulk_g2s(s2u(smem + SM_CS_OFF) + st*(KCH*16), &g_Sa[(size_t)kc*4], KCH*16, m);
    }
  };

  if (total > 0) issue(0);
  if (total > 1) issue(1);

  int seq = 0;
  for (int tIdx = 0; tIdx < ntile; tIdx++){
    const int g   = bid + tIdx*GRID4;
    const int rb0 = (g & 255)*BR;
    const int ks  = g >> 8;
    const int rbase = rb0 + warp*4;

    ull acc[4][4];
    #pragma unroll
    for (int r = 0; r < 4; r++)
      #pragma unroll
      for (int j = 0; j < 4; j++) acc[r][j] = 0ull;

    for (int c = 0; c < NCH; c++, seq++){
      const int st = seq & 1;
      mbar_wait(mb + st*8, (seq >> 1) & 1);
      const float* w4 = (const float*)(smem + SM_W_OFF) + st*(BR*KCH) + warp*4*KCH;
      const float4* cx = (const float4*)(smem + SM_CX_OFF) + st*KCH;
      const float4* cs = (const float4*)(smem + SM_CS_OFF) + st*KCH;
      #pragma unroll
      for (int kk = 0; kk < KCH; kk += 64){
        const int k0 = kk + lane;
        const int k1 = k0 + 32;
        float w0[4], w1[4];
        #pragma unroll
        for (int r = 0; r < 4; r++){
          w0[r] = w4[r*KCH + k0];
          w1[r] = w4[r*KCH + k1];
        }
        {
          ulonglong2 vx = *(const ulonglong2*)&cx[k0];
          ulonglong2 vs = *(const ulonglong2*)&cs[k0];
          #pragma unroll
          for (int r = 0; r < 4; r++){
            ull wl = pk2(w0[r], w0[r]);
            acc[r][0] = fma2(wl, vx.x, acc[r][0]);
            acc[r][1] = fma2(wl, vx.y, acc[r][1]);
            acc[r][2] = fma2(wl, vs.x, acc[r][2]);
            acc[r][3] = fma2(wl, vs.y, acc[r][3]);
          }
        }
        {
          ulonglong2 vx = *(const ulonglong2*)&cx[k1];
          ulonglong2 vs = *(const ulonglong2*)&cs[k1];
          #pragma unroll
          for (int r = 0; r < 4; r++){
            ull wl = pk2(w1[r], w1[r]);
            acc[r][0] = fma2(wl, vx.x, acc[r][0]);
            acc[r][1] = fma2(wl, vx.y, acc[r][1]);
            acc[r][2] = fma2(wl, vs.x, acc[r][2]);
            acc[r][3] = fma2(wl, vs.y, acc[r][3]);
          }
        }
      }
      __syncthreads();
      if (seq + NST < total) issue(seq + NST);
    }

    // write this tile's partials (registers only; pipeline keeps filling)
    #pragma unroll
    for (int r = 0; r < 4; r++){
      #pragma unroll
      for (int j = 0; j < 4; j++){
        ull v = acc[r][j];
        v = add2(v, __shfl_xor_sync(0xffffffffu, v, 16));
        v = add2(v, __shfl_xor_sync(0xffffffffu, v, 8));
        v = add2(v, __shfl_xor_sync(0xffffffffu, v, 4));
        v = add2(v, __shfl_xor_sync(0xffffffffu, v, 2));
        v = add2(v, __shfl_xor_sync(0xffffffffu, v, 1));
        if (lane == 0){
          float2 f = upk2(v);
          int row = rbase + r;
          if (j < 2){ g_MxP[ks][row*4 + 2*j]     = f.x; g_MxP[ks][row*4 + 2*j + 1]     = f.y; }
          else      { g_MsP[ks][row*4 + 2*(j-2)] = f.x; g_MsP[ks][row*4 + 2*(j-2) + 1] = f.y; }
        }
      }
    }
  }
}

// ---------------- k5: gates + sinusoid + dual conv; sums 8 split-K partials inline ----------------
__global__ void k5_conv(const float* __restrict__ X, const float* __restrict__ S,
                        const float* __restrict__ wx, const float* __restrict__ bx,
                        const float* __restrict__ ws, const float* __restrict__ bs,
                        float* __restrict__ out){
  __shared__ float in_s[2][8][258];
  __shared__ float wmid[2][8][8][3];
  __shared__ float bias[2][8];
  __shared__ float sins[258];
  const int t = threadIdx.x;
  const int n0 = blockIdx.x*256;

  for (int idx = t; idx < 384; idx += 256){
    int b = idx/192, rem = idx%192;
    int co = rem/24, ci = (rem%24)/3, kh = rem%3;
    const float* w = b ? ws : wx;
    wmid[b][co][ci][kh] = w[((co*8 + ci)*3 + kh)*3 + 1];
  }
  if (t < 16) bias[t>>3][t&7] = (t < 8) ? bx[t] : bs[t-8];
  for (int col = t; col < 258; col += 256)
    sins[col] = (float)sin((double)(n0 + col - 1));
  __syncthreads();

  for (int idx = t; idx < 2*8*258; idx += 256){
    int b = idx/(8*258); int rem = idx%(8*258);
    int ci = rem/258, col = rem%258;
    int n = n0 + col - 1;
    float v = 0.f;
    if (n >= 0 && n < NN){
      if (ci < 4){
        float m = 0.f;
        if (b == 0){
          #pragma unroll
          for (int ksp = 0; ksp < KSPL; ksp++) m += g_MxP[ksp][ci*NN + n];
        } else {
          #pragma unroll
          for (int ksp = 0; ksp < KSPL; ksp++) m += g_MsP[ksp][ci*NN + n];
        }
        v = m * X[ci*NN + n];
      } else {
        v = b ? S[(ci-4)*NN + n] : X[(ci-4)*NN + n];
      }
      if (b == 1) v += sins[col];
    }
    in_s[b][ci][col] = v;
  }
  __syncthreads();

  const int n = n0 + t;
  #pragma unroll
  for (int b = 0; b < 2; b++){
    #pragma unroll
    for (int co = 0; co < 8; co++){
      float a = bias[b][co];
      #pragma unroll
      for (int ci = 0; ci < 8; ci++){
        a = fmaf(wmid[b][co][ci][0], in_s[b][ci][t  ], a);
        a = fmaf(wmid[b][co][ci][1], in_s[b][ci][t+1], a);
        a = fmaf(wmid[b][co][ci][2], in_s[b][ci][t+2], a);
      }
      out[(size_t)b*8*NN + (size_t)co*NN + n] = a;
    }
  }
}

// ---------------- launch ----------------
extern "C" void kernel_launch(void* const* d_in, const int* in_sizes, int n_in,
                              void* d_out, int out_size){
  (void)in_sizes; (void)n_in; (void)out_size;
  const float* X   = (const float*)d_in[0];
  const float* S   = (const float*)d_in[1];
  const float* W1x = (const float*)d_in[2];
  const float* W1s = (const float*)d_in[3];
  const float* W2  = (const float*)d_in[4];
  const float* cwx = (const float*)d_in[5];
  const float* cbx = (const float*)d_in[6];
  const float* cws = (const float*)d_in[7];
  const float* cbs = (const float*)d_in[8];
  float* out = (float*)d_out;

  static int smem_set = 0;
  if (!smem_set){
    cudaFuncSetAttribute(k4_gemv, cudaFuncAttributeMaxDynamicSharedMemorySize, SM_TOTAL);
    smem_set = 1;
  }

  k1_embed  <<<NB1, 256>>>(X, S, W1x, W1s);
  k2_attn   <<<dim3(JBLK, IBLK, 2), 128>>>();
  k3_combine<<<256, 256>>>();
  k4_gemv   <<<GRID4, 256, SM_TOTAL>>>(W2);
  k5_conv   <<<NN/256, 256>>>(X, S, cwx, cbx, cws, cbs, out);
}